// round 15
// baseline (speedup 1.0000x reference)
#include <cuda_runtime.h>
#include <cuda_bf16.h>
#include <mma.h>
#include <cstdint>

using namespace nvcuda;

#define BDIM 8
#define TDIM 8192
#define KDIM 64
#define DDIM 128
#define SEGL 16
#define NSEG (BDIM * TDIM / SEGL)           // 4096 segments (16 steps each)
#define SEG_PER_B (TDIM / SEGL)             // 512 per batch
#define GROWS 64
#define NGBLK (BDIM * TDIM / GROWS)         // 1024 gemm blocks

// ---------------- scratch (device globals; no allocation) ----------------
__device__ float  g_u[BDIM * TDIM * KDIM];        // raw x @ W^T
__device__ float4 g_segA[NSEG * KDIM];            // (Ar, Ai, Br, Bi)
__device__ float2 g_hstart[NSEG * KDIM];          // h at segment start
__device__ float  g_inv_sigma;
__device__ __nv_bfloat16 g_Whi[KDIM * DDIM];      // W split hi
__device__ __nv_bfloat16 g_Wlo[KDIM * DDIM];      // W split lo

#define LDS_PAD 136
#define TILE_HALF (GROWS * LDS_PAD)

// =========================================================================
// Kernel 0: split W -> bf16 hi/lo in global
// =========================================================================
__global__ __launch_bounds__(128) void prep_kernel(const float* __restrict__ W)
{
    const int tid = threadIdx.x;
    #pragma unroll
    for (int i = 0; i < KDIM * DDIM / 128; i++) {
        int e = tid + 128 * i;
        float v = W[e];
        __nv_bfloat16 h = __float2bfloat16(v);
        g_Whi[e] = h;
        g_Wlo[e] = __float2bfloat16(v - __bfloat162float(h));
    }
}

// =========================================================================
// Kernel 1: u = x@W^T (wmma bf16 split hi*hi + lo*hi + hi*lo) + sigma blk 0.
// =========================================================================
__global__ __launch_bounds__(128)
void gemm_wmma_kernel(const float* __restrict__ x, const float* __restrict__ W)
{
    __shared__ __align__(16) __nv_bfloat16 sm[2 * TILE_HALF];   // 34816 B
    const int tid = threadIdx.x;

    if (blockIdx.x == 0) {
        // -------- sigma block: power iteration on W W^T (64x64) ----------
        float* Ms = (float*)sm;           // [64][65]
        float* v0 = Ms + 4160;
        float* v1 = v0 + 64;
        for (int e = tid; e < 4096; e += 128) {
            int r = e >> 6, c = e & 63;
            const float4* a = (const float4*)(W + r * DDIM);
            const float4* b = (const float4*)(W + c * DDIM);
            float s = 0.f;
            #pragma unroll
            for (int d = 0; d < 32; d++) {
                float4 av = a[d], bv = b[d];
                s += av.x*bv.x + av.y*bv.y + av.z*bv.z + av.w*bv.w;
            }
            Ms[r*65 + c] = s;
        }
        if (tid < 64) v0[tid] = 1.0f;
        __syncthreads();
        const int r = tid >> 1, part = tid & 1;
        float* va = v0; float* vb = v1;
        for (int it = 0; it < 96; it++) {
            float s = 0.f;
            #pragma unroll
            for (int j = 0; j < 32; j++)
                s += Ms[r*65 + part*32 + j] * va[part*32 + j];
            s += __shfl_xor_sync(0xffffffffu, s, 1);
            if (part == 0) vb[r] = ((it & 31) == 31) ? s * 1e-14f : s;
            __syncthreads();
            float* t = va; va = vb; vb = t;
        }
        {   // Rayleigh quotient
            float s = 0.f;
            #pragma unroll
            for (int j = 0; j < 32; j++)
                s += Ms[r*65 + part*32 + j] * va[part*32 + j];
            s += __shfl_xor_sync(0xffffffffu, s, 1);
            if (part == 0) vb[r] = s;
        }
        __syncthreads();
        if (tid == 0) {
            float num = 0.f, den = 0.f;
            for (int j = 0; j < 64; j++) { num += va[j]*vb[j]; den += va[j]*va[j]; }
            g_inv_sigma = 1.0f / sqrtf(num / den);
        }
        return;
    }

    // ---------------- GEMM block -----------------------------------------
    __nv_bfloat16* sAhi = sm;
    __nv_bfloat16* sAlo = sAhi + TILE_HALF;

    const int row0 = (blockIdx.x - 1) * GROWS;

    {   // stage x tile [64 rows][128 d] split hi/lo
        const float4* xb = (const float4*)(x + (size_t)row0 * DDIM);
        #pragma unroll
        for (int i = 0; i < 16; i++) {
            int e = tid + 128 * i;
            int r = e >> 5, c4 = e & 31;
            float4 v = xb[e];
            __nv_bfloat16* dh = &sAhi[r * LDS_PAD + c4 * 4];
            __nv_bfloat16* dl = &sAlo[r * LDS_PAD + c4 * 4];
            float vv[4] = {v.x, v.y, v.z, v.w};
            #pragma unroll
            for (int q = 0; q < 4; q++) {
                __nv_bfloat16 h = __float2bfloat16(vv[q]);
                dh[q] = h;
                dl[q] = __float2bfloat16(vv[q] - __bfloat162float(h));
            }
        }
    }
    __syncthreads();

    const int w = tid >> 5;
    wmma::fragment<wmma::accumulator, 16, 16, 16, float> fc[4];
    #pragma unroll
    for (int nt = 0; nt < 4; nt++) wmma::fill_fragment(fc[nt], 0.0f);

    wmma::fragment<wmma::matrix_a, 16, 16, 16, __nv_bfloat16, wmma::row_major> fahi, falo;
    wmma::fragment<wmma::matrix_b, 16, 16, 16, __nv_bfloat16, wmma::col_major> fbhi, fblo;

    const __nv_bfloat16* As = sAhi + (w * 16) * LDS_PAD;
    const __nv_bfloat16* Al = sAlo + (w * 16) * LDS_PAD;

    #pragma unroll
    for (int kk = 0; kk < 8; kk++) {
        wmma::load_matrix_sync(fahi, As + kk * 16, LDS_PAD);
        wmma::load_matrix_sync(falo, Al + kk * 16, LDS_PAD);
        #pragma unroll
        for (int nt = 0; nt < 4; nt++) {
            wmma::load_matrix_sync(fbhi, g_Whi + (nt * 16) * DDIM + kk * 16, DDIM);
            wmma::mma_sync(fc[nt], fahi, fbhi, fc[nt]);   // hi*hi
            wmma::mma_sync(fc[nt], falo, fbhi, fc[nt]);   // lo*hi
            wmma::load_matrix_sync(fblo, g_Wlo + (nt * 16) * DDIM + kk * 16, DDIM);
            wmma::mma_sync(fc[nt], fahi, fblo, fc[nt]);   // hi*lo
        }
    }

    float* outp = &g_u[(size_t)(row0 + w * 16) * KDIM];
    #pragma unroll
    for (int nt = 0; nt < 4; nt++)
        wmma::store_matrix_sync(outp + nt * 16, fc[nt], KDIM, wmma::mem_row_major);
}

// =========================================================================
// Kernel 2: per-segment aggregates, sigma+bias folded in. Grid 1024 x 256.
// =========================================================================
__global__ __launch_bounds__(256) void aggregate_kernel(
    const float* __restrict__ dt,   const float* __restrict__ amod,
    const float* __restrict__ omod, const float* __restrict__ tmod,
    const float* __restrict__ srr,  const float* __restrict__ sim,
    const float* __restrict__ traw, const float* __restrict__ bias)
{
    const int tid = threadIdx.x;
    const int k   = tid & 63;
    const int seg = blockIdx.x * 4 + (tid >> 6);
    const int t0  = seg * SEGL;

    float tr  = traw[0];
    float tau = ((tr > 20.f) ? tr : log1pf(expf(tr))) + 1e-3f;
    float sr  = srr[k];
    float sp  = (sr > 20.f) ? sr : log1pf(expf(sr));
    float alpha0 = (sp + 1e-6f) * tau;
    float omega0 = sim[k] * tau;
    float bk     = bias[k];
    float invsig = g_inv_sigma;

    float cr[SEGL], ci[SEGL], uu[SEGL];
    #pragma unroll
    for (int i = 0; i < SEGL; i++) {
        int bt = t0 + i;
        size_t idx = (size_t)bt * KDIM + k;
        float tv  = tmod[bt];
        float dtv = dt[bt];
        float alpha = alpha0 * __expf(amod[idx] + tv);
        float omega = omega0 * __expf(omod[idx] + tv);
        float rho   = __expf(-alpha * dtv);
        float sn, cs; __sincosf(omega * dtv, &sn, &cs);
        cr[i] = rho * cs; ci[i] = rho * sn;
        uu[i] = g_u[idx] * invsig + bk;
    }

    float Ar = 1.f, Ai = 0.f, Br = 0.f, Bi = 0.f;
    #pragma unroll
    for (int i = 0; i < SEGL; i++) {
        float car = cr[i], cai = ci[i];
        float nbr = car*Br - cai*Bi + uu[i];
        float nbi = car*Bi + cai*Br;
        float nar = car*Ar - cai*Ai;
        float nai = car*Ai + cai*Ar;
        Br = nbr; Bi = nbi; Ar = nar; Ai = nai;
    }
    g_segA[(size_t)seg * KDIM + k] = make_float4(Ar, Ai, Br, Bi);
}

// =========================================================================
// Kernel 3: FUSED scan. Grid 8 x 1024 (one block per batch).
// 16 groups x 64 k; group g owns segments [g*32, g*32+32) of the batch.
// Phase 1: group aggregates (prefetch-4-then-chain).
// Phase 2: 64 threads scan the 16 group aggregates in smem.
// Phase 3: rewalk, write h_start for all 512 segments of the batch.
// =========================================================================
__global__ __launch_bounds__(1024) void scanfuse_kernel()
{
    __shared__ float4 sG[16][KDIM];
    __shared__ float4 sP[16][KDIM];

    const int tid = threadIdx.x;
    const int k   = tid & 63;
    const int g   = tid >> 6;        // 0..15
    const int b   = blockIdx.x;
    const size_t base = ((size_t)b * SEG_PER_B + g * 32) * KDIM + k;

    // ---- phase 1: combine own 32 segments -------------------------------
    float Ar = 1.f, Ai = 0.f, Br = 0.f, Bi = 0.f;
    #pragma unroll
    for (int q = 0; q < 8; q++) {
        float4 v[4];
        #pragma unroll
        for (int j = 0; j < 4; j++)
            v[j] = g_segA[base + (size_t)(q * 4 + j) * KDIM];
        #pragma unroll
        for (int j = 0; j < 4; j++) {
            float nAr = v[j].x*Ar - v[j].y*Ai;
            float nAi = v[j].x*Ai + v[j].y*Ar;
            float nBr = v[j].x*Br - v[j].y*Bi + v[j].z;
            float nBi = v[j].x*Bi + v[j].y*Br + v[j].w;
            Ar = nAr; Ai = nAi; Br = nBr; Bi = nBi;
        }
    }
    sG[g][k] = make_float4(Ar, Ai, Br, Bi);
    __syncthreads();

    // ---- phase 2: exclusive scan over 16 groups (threads 0..63) ---------
    if (tid < 64) {
        float EAr = 1.f, EAi = 0.f, EBr = 0.f, EBi = 0.f;
        #pragma unroll
        for (int gg = 0; gg < 16; gg++) {
            sP[gg][k] = make_float4(EAr, EAi, EBr, EBi);
            float4 v = sG[gg][k];
            float nAr = v.x*EAr - v.y*EAi;
            float nAi = v.x*EAi + v.y*EAr;
            float nBr = v.x*EBr - v.y*EBi + v.z;
            float nBi = v.x*EBi + v.y*EBr + v.w;
            EAr = nAr; EAi = nAi; EBr = nBr; EBi = nBi;
        }
    }
    __syncthreads();

    // ---- phase 3: rewalk own 32 segments, emit h_start ------------------
    float4 E = sP[g][k];
    float EAr = E.x, EAi = E.y, EBr = E.z, EBi = E.w;
    #pragma unroll
    for (int q = 0; q < 8; q++) {
        float4 v[4];
        #pragma unroll
        for (int j = 0; j < 4; j++)
            v[j] = g_segA[base + (size_t)(q * 4 + j) * KDIM];
        #pragma unroll
        for (int j = 0; j < 4; j++) {
            g_hstart[base + (size_t)(q * 4 + j) * KDIM] = make_float2(EBr, EBi);
            float nAr = v[j].x*EAr - v[j].y*EAi;
            float nAi = v[j].x*EAi + v[j].y*EAr;
            float nBr = v[j].x*EBr - v[j].y*EBi + v[j].z;
            float nBi = v[j].x*EBi + v[j].y*EBr + v[j].w;
            EAr = nAr; EAi = nAi; EBr = nBr; EBi = nBi;
        }
    }
}

// =========================================================================
// Kernel 4: apply pass. Thread = (segment, k). Prefetch-then-chain.
// =========================================================================
__global__ __launch_bounds__(256) void apply_kernel(
    const float* __restrict__ dt,   const float* __restrict__ amod,
    const float* __restrict__ omod, const float* __restrict__ tmod,
    const float* __restrict__ srr,  const float* __restrict__ sim,
    const float* __restrict__ traw, const float* __restrict__ bias,
    float* __restrict__ out)
{
    const int tid = threadIdx.x;
    const int k   = tid & 63;
    const int seg = blockIdx.x * 4 + (tid >> 6);
    const int t0  = seg * SEGL;

    float tr  = traw[0];
    float tau = ((tr > 20.f) ? tr : log1pf(expf(tr))) + 1e-3f;
    float sr  = srr[k];
    float sp  = (sr > 20.f) ? sr : log1pf(expf(sr));
    float alpha0 = (sp + 1e-6f) * tau;
    float omega0 = sim[k] * tau;
    float bk     = bias[k];
    float invsig = g_inv_sigma;

    float cr[SEGL], ci[SEGL], uu[SEGL];
    #pragma unroll
    for (int i = 0; i < SEGL; i++) {
        int bt = t0 + i;
        size_t idx = (size_t)bt * KDIM + k;
        float tv  = tmod[bt];
        float dtv = dt[bt];
        float alpha = alpha0 * __expf(amod[idx] + tv);
        float omega = omega0 * __expf(omod[idx] + tv);
        float rho   = __expf(-alpha * dtv);
        float sn, cs; __sincosf(omega * dtv, &sn, &cs);
        cr[i] = rho * cs; ci[i] = rho * sn;
        uu[i] = g_u[idx] * invsig + bk;
    }

    float2 h = g_hstart[(size_t)seg * KDIM + k];
    float hr = h.x, hi = h.y;

    #pragma unroll
    for (int i = 0; i < SEGL; i++) {
        float nr = cr[i]*hr - ci[i]*hi + uu[i];
        float ni = cr[i]*hi + ci[i]*hr;
        hr = nr; hi = ni;
        size_t ob = (size_t)(t0 + i) * (2 * KDIM);
        out[ob + k]        = hr;   // C
        out[ob + KDIM + k] = hi;   // S
    }
}

// =========================================================================
extern "C" void kernel_launch(void* const* d_in, const int* in_sizes, int n_in,
                              void* d_out, int out_size)
{
    (void)in_sizes; (void)n_in; (void)out_size;
    const float* x    = (const float*)d_in[0];
    const float* dt   = (const float*)d_in[1];
    const float* amod = (const float*)d_in[2];
    const float* omod = (const float*)d_in[3];
    const float* tmod = (const float*)d_in[4];
    const float* srr  = (const float*)d_in[5];
    const float* sim  = (const float*)d_in[6];
    const float* traw = (const float*)d_in[7];
    const float* W    = (const float*)d_in[8];
    const float* bias = (const float*)d_in[9];
    float* out = (float*)d_out;

    prep_kernel<<<1, 128>>>(W);
    gemm_wmma_kernel<<<NGBLK + 1, 128>>>(x, W);
    aggregate_kernel<<<NSEG / 4, 256>>>(dt, amod, omod, tmod, srr, sim, traw, bias);
    scanfuse_kernel<<<BDIM, 1024>>>();
    apply_kernel<<<NSEG / 4, 256>>>(dt, amod, omod, tmod, srr, sim, traw, bias, out);
}